// round 11
// baseline (speedup 1.0000x reference)
#include <cuda_runtime.h>
#include <cuda_bf16.h>
#include <math.h>
#include <stdint.h>

typedef __nv_bfloat16 bf16;

// ---------------------------------------------------------------------------
// Frame-major dataflow, F = 8192:
//  magT(Xh/Xl)[F,2112] -> E1[F,1024] -> Cat[F,712] (H 0..200 | E 200..712)
//  -> Gx[F,896] f32 -> scan -> Cat H -> T1[F,896] -> T2[F,512] -> D[F,1024]
//  -> out[2049,F]
// bf16 hi/lo split everywhere (hi+lo ~ fp32@2^-17); weight pads are ZERO.
// GEMMs on tensor cores via mma.sync m16n8k16 (tcgen05 unavailable at
// compute_100 PTX target).  GEMM kernel is VERBATIM the round-9 version
// that measured 6547us; only the scan changed this round (512 threads,
// shfl UB removed: all lanes participate, only the sgate write is guarded).
// ---------------------------------------------------------------------------
#define FF 8192

__device__ __align__(16) bf16 g_Xh [FF * 2112], g_Xl [FF * 2112];
__device__ __align__(16) bf16 g_W1h[1024 * 2112], g_W1l[1024 * 2112];
__device__ __align__(16) bf16 g_W2h[ 512 * 1024], g_W2l[ 512 * 1024];
__device__ __align__(16) bf16 g_Wih_h[896 * 512], g_Wih_l[896 * 512];
__device__ __align__(16) bf16 g_Wf1h[896 * 640],  g_Wf1l[896 * 640];
__device__ __align__(16) bf16 g_Wf2h[512 * 896],  g_Wf2l[512 * 896];
__device__ __align__(16) bf16 g_W3h[1024 * 512],  g_W3l[1024 * 512];
__device__ __align__(16) bf16 g_W4h[2176 * 1024], g_W4l[2176 * 1024];
__device__ __align__(16) bf16 g_E1h[FF * 1024],   g_E1l[FF * 1024];
__device__ __align__(16) bf16 g_Cath[FF * 712],   g_Catl[FF * 712];
__device__ __align__(16) float g_Gx [FF * 896];
__device__ __align__(16) bf16 g_T1h[FF * 896],    g_T1l[FF * 896];
__device__ __align__(16) bf16 g_T2h[FF * 512],    g_T2l[FF * 512];
__device__ __align__(16) bf16 g_Dh [FF * 1024],   g_Dl [FF * 1024];
__device__ float g_bsum[800];

__device__ __forceinline__ float sigf(float x) { return 1.0f / (1.0f + expf(-x)); }
__device__ __forceinline__ float tanha(float x) {
    float y; asm("tanh.approx.f32 %0, %1;" : "=f"(y) : "f"(x)); return y;
}
__device__ __forceinline__ float siga(float x) {
    return 0.5f * tanha(0.5f * x) + 0.5f;
}
__device__ __forceinline__ uint32_t s2u(const void* p) {
    uint32_t a;
    asm("{ .reg .u64 t; cvta.to.shared.u64 t, %1; cvt.u32.u64 %0, t; }"
        : "=r"(a) : "l"(p));
    return a;
}
__device__ __forceinline__ void mbar_wait(uint32_t ba, uint32_t par) {
    uint32_t done;
    asm volatile(
        "{\n\t.reg .pred p;\n\t"
        "mbarrier.try_wait.parity.acquire.cta.shared::cta.b64 p, [%1], %2;\n\t"
        "selp.b32 %0, 1, 0, p;\n\t}"
        : "=r"(done) : "r"(ba), "r"(par) : "memory");
    if (!done) {
        asm volatile(
            "{\n\t.reg .pred P1;\n\t"
            "WL_%=:\n\t"
            "mbarrier.try_wait.parity.acquire.cta.shared::cta.b64 P1, [%0], %1, 0x989680;\n\t"
            "@P1 bra.uni WD_%=;\n\t"
            "bra.uni WL_%=;\n\t"
            "WD_%=:\n\t}"
            :: "r"(ba), "r"(par) : "memory");
    }
}
// packed f32x2 (scan)
__device__ __forceinline__ void fma2(unsigned long long& acc,
                                     unsigned long long a, unsigned long long b) {
    asm("fma.rn.f32x2 %0, %1, %2, %0;" : "+l"(acc) : "l"(a), "l"(b));
}
__device__ __forceinline__ unsigned long long pack2(float x, float y) {
    unsigned long long v;
    asm("mov.b64 %0, {%1, %2};" : "=l"(v) : "f"(x), "f"(y));
    return v;
}
__device__ __forceinline__ void unpack2(float& lo, float& hi, unsigned long long v) {
    asm("mov.b64 {%0, %1}, %2;" : "=f"(lo), "=f"(hi) : "l"(v));
}

// mma.sync m16n8k16 bf16 (row.col), f32 accum
__device__ __forceinline__ void mma16816(float d[4],
                                         uint32_t a0, uint32_t a1,
                                         uint32_t a2, uint32_t a3,
                                         uint32_t b0, uint32_t b1) {
    asm volatile(
        "mma.sync.aligned.m16n8k16.row.col.f32.bf16.bf16.f32 "
        "{%0,%1,%2,%3}, {%4,%5,%6,%7}, {%8,%9}, {%0,%1,%2,%3};"
        : "+f"(d[0]), "+f"(d[1]), "+f"(d[2]), "+f"(d[3])
        : "r"(a0), "r"(a1), "r"(a2), "r"(a3), "r"(b0), "r"(b1));
}

// ---------------------------------------------------------------------------
// mma_gemm<ACT> — VERBATIM round-9 (measured 6547us total, PASS).
// D[128f x 128c] per CTA, 256 threads (8 warps, each 64x32).  K in
// 64-chunks, single-buffer smem, pitch 72 bf16.  3 MMAs per tile (split).
// ---------------------------------------------------------------------------
template <int ACT>
__global__ void __launch_bounds__(256) mma_gemm(
    const bf16* __restrict__ Ah, const bf16* __restrict__ Al, int lda,
    const bf16* __restrict__ Wh, const bf16* __restrict__ Wl, int Kpad,
    const float* __restrict__ bias, int M,
    bf16* __restrict__ Chi, bf16* __restrict__ Clo, float* __restrict__ Cf,
    int ldc, int cofs,
    const float* __restrict__ mag, float* __restrict__ outp, int F)
{
    constexpr int P  = 72;   // smem pitch (bf16)
    constexpr int PW = 36;   // smem pitch (32-bit words)
    extern __shared__ bf16 smg[];
    bf16* sAh = smg;
    bf16* sAl = sAh + 128 * P;
    bf16* sWh = sAl + 128 * P;
    bf16* sWl = sWh + 128 * P;        // total 73728 B

    const int tid  = threadIdx.x;
    const int w    = tid >> 5;
    const int lane = tid & 31;
    const int g    = lane >> 2;
    const int tg   = lane & 3;
    const int wm   = (w & 1) * 64;
    const int wn   = (w >> 1) * 32;
    const int f0   = blockIdx.x * 128;
    const int m0   = blockIdx.y * 128;
    const int lrow = tid >> 1;
    const int lcol = (tid & 1) * 32;

    const uint32_t* s32Ah = reinterpret_cast<const uint32_t*>(sAh);
    const uint32_t* s32Al = reinterpret_cast<const uint32_t*>(sAl);
    const uint32_t* s32Wh = reinterpret_cast<const uint32_t*>(sWh);
    const uint32_t* s32Wl = reinterpret_cast<const uint32_t*>(sWl);

    float acc[4][4][4];
#pragma unroll
    for (int mt = 0; mt < 4; mt++)
#pragma unroll
        for (int nt = 0; nt < 4; nt++)
#pragma unroll
            for (int q = 0; q < 4; q++) acc[mt][nt][q] = 0.0f;

    const int NC = Kpad >> 6;
    for (int ci = 0; ci < NC; ci++) {
        const int k0 = ci << 6;
        uint4 rA[4], rB[4], rC[4], rD[4];
        {
            const uint4* pA = reinterpret_cast<const uint4*>(
                Ah + (size_t)(f0 + lrow) * lda + k0 + lcol);
            const uint4* pB = reinterpret_cast<const uint4*>(
                Al + (size_t)(f0 + lrow) * lda + k0 + lcol);
            const uint4* pC = reinterpret_cast<const uint4*>(
                Wh + (size_t)(m0 + lrow) * Kpad + k0 + lcol);
            const uint4* pD = reinterpret_cast<const uint4*>(
                Wl + (size_t)(m0 + lrow) * Kpad + k0 + lcol);
#pragma unroll
            for (int i = 0; i < 4; i++) {
                rA[i] = pA[i]; rB[i] = pB[i]; rC[i] = pC[i]; rD[i] = pD[i];
            }
        }
        __syncthreads();              // previous chunk's compute done
        {
            uint4* dA = reinterpret_cast<uint4*>(sAh + lrow * P + lcol);
            uint4* dB = reinterpret_cast<uint4*>(sAl + lrow * P + lcol);
            uint4* dC = reinterpret_cast<uint4*>(sWh + lrow * P + lcol);
            uint4* dD = reinterpret_cast<uint4*>(sWl + lrow * P + lcol);
#pragma unroll
            for (int i = 0; i < 4; i++) {
                dA[i] = rA[i]; dB[i] = rB[i]; dC[i] = rC[i]; dD[i] = rD[i];
            }
        }
        __syncthreads();

#pragma unroll
        for (int kk = 0; kk < 4; kk++) {
            uint32_t bh[4][2], bl[4][2];
#pragma unroll
            for (int nt = 0; nt < 4; nt++) {
                int br = (wn + nt * 8 + g) * PW + kk * 8 + tg;
                bh[nt][0] = s32Wh[br];      bh[nt][1] = s32Wh[br + 4];
                bl[nt][0] = s32Wl[br];      bl[nt][1] = s32Wl[br + 4];
            }
#pragma unroll
            for (int mt = 0; mt < 4; mt++) {
                int ar = (wm + mt * 16 + g) * PW + kk * 8 + tg;
                uint32_t ah0 = s32Ah[ar];
                uint32_t ah1 = s32Ah[ar + 8 * PW];
                uint32_t ah2 = s32Ah[ar + 4];
                uint32_t ah3 = s32Ah[ar + 8 * PW + 4];
                uint32_t al0 = s32Al[ar];
                uint32_t al1 = s32Al[ar + 8 * PW];
                uint32_t al2 = s32Al[ar + 4];
                uint32_t al3 = s32Al[ar + 8 * PW + 4];
#pragma unroll
                for (int nt = 0; nt < 4; nt++) {
                    mma16816(acc[mt][nt], ah0, ah1, ah2, ah3, bh[nt][0], bh[nt][1]);
                    mma16816(acc[mt][nt], al0, al1, al2, al3, bh[nt][0], bh[nt][1]);
                    mma16816(acc[mt][nt], ah0, ah1, ah2, ah3, bl[nt][0], bl[nt][1]);
                }
            }
        }
    }

    // ---- epilogue ----
#pragma unroll
    for (int mt = 0; mt < 4; mt++) {
        const int fa = f0 + wm + mt * 16 + g;
#pragma unroll
        for (int nt = 0; nt < 4; nt++) {
            const int c0 = m0 + wn + nt * 8 + 2 * tg;
            const float bv0 = (c0 < M)     ? __ldg(&bias[c0])     : 0.0f;
            const float bv1 = (c0 + 1 < M) ? __ldg(&bias[c0 + 1]) : 0.0f;
#pragma unroll
            for (int hrow = 0; hrow < 2; hrow++) {
                const int f = fa + hrow * 8;
                float v0 = acc[mt][nt][2 * hrow]     + bv0;
                float v1 = acc[mt][nt][2 * hrow + 1] + bv1;
                if (ACT == 0) {
                    v0 = (v0 >= 0.0f) ? v0 : 0.01f * v0;
                    v1 = (v1 >= 0.0f) ? v1 : 0.01f * v1;
                    bf16 h0 = __float2bfloat16(v0);
                    bf16 h1 = __float2bfloat16(v1);
                    bf16 l0 = __float2bfloat16(v0 - __bfloat162float(h0));
                    bf16 l1 = __float2bfloat16(v1 - __bfloat162float(h1));
                    uint32_t hw = ((uint32_t)__bfloat16_as_ushort(h1) << 16)
                                  | __bfloat16_as_ushort(h0);
                    uint32_t lw = ((uint32_t)__bfloat16_as_ushort(l1) << 16)
                                  | __bfloat16_as_ushort(l0);
                    size_t off = (size_t)f * ldc + cofs + c0;
                    *reinterpret_cast<uint32_t*>(Chi + off) = hw;
                    *reinterpret_cast<uint32_t*>(Clo + off) = lw;
                } else if (ACT == 1) {
                    *reinterpret_cast<float2*>(Cf + (size_t)f * ldc + c0) =
                        make_float2(v0, v1);
                } else {
                    if (c0 < 2049) {
                        size_t idx = (size_t)c0 * F + f;
                        outp[idx] = sigf(v0) * __ldg(&mag[idx]);
                    }
                    if (c0 + 1 < 2049) {
                        size_t idx = (size_t)(c0 + 1) * F + f;
                        outp[idx] = sigf(v1) * __ldg(&mag[idx]);
                    }
                }
            }
        }
    }
}

// ---------------------------------------------------------------------------
// prep kernels
// ---------------------------------------------------------------------------
__global__ void bias_sum_kernel(const float* __restrict__ a,
                                const float* __restrict__ b,
                                float* __restrict__ out, int n)
{
    int i = blockIdx.x * blockDim.x + threadIdx.x;
    if (i < n) out[i] = a[i] + b[i];
}

__global__ void split_weight(const float* __restrict__ W, int M, int K,
                             bf16* __restrict__ Wh, bf16* __restrict__ Wl,
                             int Mp, int Kp)
{
    int i = blockIdx.x * blockDim.x + threadIdx.x;
    if (i >= Mp * Kp) return;
    int r = i / Kp, c = i - r * Kp;
    float v = (r < M && c < K) ? W[(size_t)r * K + c] : 0.0f;
    bf16 h = __float2bfloat16(v);
    Wh[i] = h;
    Wl[i] = __float2bfloat16(v - __bfloat162float(h));
}

// mag[2049,F] -> Xh/Xl [F,2112] (transposed, split, zero-padded)
__global__ void transpose_split_mag(const float* __restrict__ mag,
                                    bf16* __restrict__ Xh, bf16* __restrict__ Xl,
                                    int F)
{
    __shared__ float sm[32][33];
    const int ft = blockIdx.x * 32, ct = blockIdx.y * 32;
    const int tx = threadIdx.x, ty = threadIdx.y;
#pragma unroll
    for (int i = 0; i < 4; i++) {
        int c = ct + ty + i * 8;
        sm[ty + i * 8][tx] = (c < 2049) ? mag[(size_t)c * F + ft + tx] : 0.0f;
    }
    __syncthreads();
#pragma unroll
    for (int i = 0; i < 4; i++) {
        int f = ft + ty + i * 8;
        int c = ct + tx;
        float v = sm[tx][ty + i * 8];
        bf16 h = __float2bfloat16(v);
        size_t idx = (size_t)f * 2112 + c;
        Xh[idx] = h;
        Xl[idx] = __float2bfloat16(v - __bfloat162float(h));
    }
}

// ---------------------------------------------------------------------------
// LSTM scan v5b: 512 threads, UB-free.  4 threads per gate row (qi-split
// GEMV over a padded h layout, R4-proven math); shfl butterfly executed by
// ALL lanes of every warp (invalid rows compute on zero weights -> full
// 0xffffffff mask is correct by construction); only the sgate write is
// guarded.  Sync = R5-proven mbarrier ping-pong, byte-for-byte: per step
// GEMV -> syncthreads -> tid<25 update + st.shared::cluster (padded
// offsets, next buffer) -> syncthreads (drains DSMEM STS) -> tid0 remote
// arrives on bars[t&1] (count 8) -> all threads try_wait local.
// ---------------------------------------------------------------------------
__global__ void __cluster_dims__(8, 1, 1) __launch_bounds__(512, 1)
lstm_scan_kernel(const float* __restrict__ Whh, const float* __restrict__ Gx,
                 bf16* __restrict__ CatH, bf16* __restrict__ CatL, int F)
{
    __shared__ __align__(16) float hbuf[2][256];   // padded h, dbl buffered
    __shared__ float sgate[100];
    __shared__ __align__(8) unsigned long long bars[2];

    const int tid  = threadIdx.x;
    const int rank = blockIdx.x;
    const int row  = tid >> 2;     // gate row (0..127; <100 valid)
    const int qi   = tid & 3;      // quarter of padded cols
    const bool valid = row < 100;
    const int g    = row / 25;
    const int j    = row % 25;
    const int grow = 200 * g + 25 * rank + j;   // only used when valid

    // ---- weights in registers, padded-col order (zero for invalid rows) ----
    unsigned long long w[32];
#pragma unroll
    for (int k = 0; k < 32; k++) {
        float f0 = 0.0f, f1 = 0.0f;
        if (valid) {
            int c0 = qi * 64 + 2 * k;
            int s0 = c0 >> 5, o0 = c0 & 31;
            int c1 = c0 + 1;
            int s1 = c1 >> 5, o1 = c1 & 31;
            if (o0 < 25) f0 = Whh[(size_t)grow * 200 + s0 * 25 + o0];
            if (o1 < 25) f1 = Whh[(size_t)grow * 200 + s1 * 25 + o1];
        }
        w[k] = pack2(f0, f1);
    }

    hbuf[tid >> 8][tid & 255] = 0.0f;     // 512 threads cover both buffers
    if (tid == 0) {
        asm volatile("mbarrier.init.shared.b64 [%0], 8;"
                     :: "r"(s2u(&bars[0])) : "memory");
        asm volatile("mbarrier.init.shared.b64 [%0], 8;"
                     :: "r"(s2u(&bars[1])) : "memory");
    }
    __syncthreads();

    const uint32_t hb_local  = s2u(&hbuf[0][0]);
    const uint32_t bar_delta = s2u(&bars[0]) - hb_local;
    uint32_t peer_h[8];
#pragma unroll
    for (int r = 0; r < 8; r++)
        asm("mapa.shared::cluster.u32 %0, %1, %2;"
            : "=r"(peer_h[r]) : "r"(hb_local), "r"(r));

    asm volatile("barrier.cluster.arrive.aligned;" ::: "memory");
    asm volatile("barrier.cluster.wait.aligned;"   ::: "memory");

    const bool lead = (qi == 0) && valid;
    float c_state = 0.0f;                 // tid<25 owns c[25*rank+tid]
    float gx_cur = lead ? __ldg(&Gx[grow]) : 0.0f;
    int ph[2] = {0, 0};

    for (int t = 0; t < F; t++) {
        const int pb = t & 1;
        float gx_next = (lead && (t + 1 < F))
                          ? __ldg(&Gx[(size_t)(t + 1) * 896 + grow]) : 0.0f;

        // ---- GEMV quarter: ALL threads execute (zero weights if invalid) ----
        {
            const ulonglong2* h4 = reinterpret_cast<const ulonglong2*>(
                &hbuf[pb][qi * 64]);
            unsigned long long acc = 0ULL;
#pragma unroll
            for (int k = 0; k < 16; k++) {
                ulonglong2 hv = h4[k];
                fma2(acc, w[2 * k],     hv.x);
                fma2(acc, w[2 * k + 1], hv.y);
            }
            float lo, hi;
            unpack2(lo, hi, acc);
            float s = lo + hi;
            s += __shfl_xor_sync(0xffffffffu, s, 1);   // all 32 lanes active
            s += __shfl_xor_sync(0xffffffffu, s, 2);
            if (lead) sgate[row] = s + gx_cur;
        }
        gx_cur = gx_next;
        __syncthreads();

        // ---- LSTM update + push h slice (padded layout, next buffer) ----
        if (tid < 25) {
            float gi = sgate[tid];
            float gf = sgate[25 + tid];
            float gg = sgate[50 + tid];
            float go = sgate[75 + tid];
            float cn = siga(gf) * c_state + siga(gi) * tanha(gg);
            float hn = siga(go) * tanha(cn);
            c_state = cn;
            size_t cidx = (size_t)t * 712 + 25 * rank + tid;
            bf16 hh = __float2bfloat16(hn);
            CatH[cidx] = hh;
            CatL[cidx] = __float2bfloat16(hn - __bfloat162float(hh));
            uint32_t off = (uint32_t)((((t + 1) & 1) * 256 + rank * 32 + tid) * 4);
#pragma unroll
            for (int r = 0; r < 8; r++)
                asm volatile("st.shared::cluster.f32 [%0], %1;"
                             :: "r"(peer_h[r] + off), "f"(hn) : "memory");
        }

        __syncthreads();   // BAR.SYNC drains DSMEM STS before the signal

        if (tid == 0) {
#pragma unroll
            for (int r = 0; r < 8; r++) {
                uint32_t ba = peer_h[r] + bar_delta + (uint32_t)(pb * 8);
                asm volatile("mbarrier.arrive.shared::cluster.b64 _, [%0];"
                             :: "r"(ba) : "memory");
            }
        }
        mbar_wait(s2u(&bars[pb]), (uint32_t)ph[pb]);
        ph[pb] ^= 1;
    }

    asm volatile("barrier.cluster.arrive.aligned;" ::: "memory");
    asm volatile("barrier.cluster.wait.aligned;"   ::: "memory");
}

// ---------------------------------------------------------------------------
// launch
// ---------------------------------------------------------------------------
extern "C" void kernel_launch(void* const* d_in, const int* in_sizes, int n_in,
                              void* d_out, int out_size)
{
    const float* mag = (const float*)d_in[0];
    const float* W1  = (const float*)d_in[1];
    const float* b1  = (const float*)d_in[2];
    const float* W2  = (const float*)d_in[3];
    const float* b2  = (const float*)d_in[4];
    const float* W3  = (const float*)d_in[5];
    const float* b3  = (const float*)d_in[6];
    const float* W4  = (const float*)d_in[7];
    const float* b4  = (const float*)d_in[8];
    const float* Wf1 = (const float*)d_in[9];
    const float* bf1 = (const float*)d_in[10];
    const float* Wf2 = (const float*)d_in[11];
    const float* bf2 = (const float*)d_in[12];
    const float* Wih = (const float*)d_in[13];
    const float* bih = (const float*)d_in[14];
    const float* Whh = (const float*)d_in[15];
    const float* bhh = (const float*)d_in[16];

    const int F = in_sizes[0] / 2049;
    float* out = (float*)d_out;

    bf16 *Xh, *Xl, *W1h, *W1l, *W2h, *W2l, *Wihh, *Wihl, *Wf1h, *Wf1l;
    bf16 *Wf2h, *Wf2l, *W3h, *W3l, *W4h, *W4l;
    bf16 *E1h, *E1l, *Cath, *Catl, *T1h, *T1l, *T2h, *T2l, *Dh, *Dl;
    float *Gx, *bsum;
    cudaGetSymbolAddress((void**)&Xh, g_Xh);     cudaGetSymbolAddress((void**)&Xl, g_Xl);
    cudaGetSymbolAddress((void**)&W1h, g_W1h);   cudaGetSymbolAddress((void**)&W1l, g_W1l);
    cudaGetSymbolAddress((void**)&W2h, g_W2h);   cudaGetSymbolAddress((void**)&W2l, g_W2l);
    cudaGetSymbolAddress((void**)&Wihh, g_Wih_h);cudaGetSymbolAddress((void**)&Wihl, g_Wih_l);
    cudaGetSymbolAddress((void**)&Wf1h, g_Wf1h); cudaGetSymbolAddress((void**)&Wf1l, g_Wf1l);
    cudaGetSymbolAddress((void**)&Wf2h, g_Wf2h); cudaGetSymbolAddress((void**)&Wf2l, g_Wf2l);
    cudaGetSymbolAddress((void**)&W3h, g_W3h);   cudaGetSymbolAddress((void**)&W3l, g_W3l);
    cudaGetSymbolAddress((void**)&W4h, g_W4h);   cudaGetSymbolAddress((void**)&W4l, g_W4l);
    cudaGetSymbolAddress((void**)&E1h, g_E1h);   cudaGetSymbolAddress((void**)&E1l, g_E1l);
    cudaGetSymbolAddress((void**)&Cath, g_Cath); cudaGetSymbolAddress((void**)&Catl, g_Catl);
    cudaGetSymbolAddress((void**)&T1h, g_T1h);   cudaGetSymbolAddress((void**)&T1l, g_T1l);
    cudaGetSymbolAddress((void**)&T2h, g_T2h);   cudaGetSymbolAddress((void**)&T2l, g_T2l);
    cudaGetSymbolAddress((void**)&Dh, g_Dh);     cudaGetSymbolAddress((void**)&Dl, g_Dl);
    cudaGetSymbolAddress((void**)&Gx, g_Gx);
    cudaGetSymbolAddress((void**)&bsum, g_bsum);

    const int SM = 4 * 128 * 72 * 2;   // 73728 B
    cudaFuncSetAttribute(mma_gemm<0>, cudaFuncAttributeMaxDynamicSharedMemorySize, SM);
    cudaFuncSetAttribute(mma_gemm<1>, cudaFuncAttributeMaxDynamicSharedMemorySize, SM);
    cudaFuncSetAttribute(mma_gemm<2>, cudaFuncAttributeMaxDynamicSharedMemorySize, SM);

    // ---- prep ----
    bias_sum_kernel<<<4, 256>>>(bih, bhh, bsum, 800);
    transpose_split_mag<<<dim3(F / 32, 66), dim3(32, 8)>>>(mag, Xh, Xl, F);
    auto swl = [&](const float* W, int M, int K, bf16* Wh_, bf16* Wl_, int Mp, int Kp) {
        split_weight<<<(Mp * Kp + 255) / 256, 256>>>(W, M, K, Wh_, Wl_, Mp, Kp);
    };
    swl(W1, 1000, 2049, W1h, W1l, 1024, 2112);
    swl(W2,  400, 1000, W2h, W2l,  512, 1024);
    swl(Wih, 800,  400, Wihh, Wihl, 896, 512);
    swl(Wf1, 800,  600, Wf1h, Wf1l, 896, 640);
    swl(Wf2, 400,  800, Wf2h, Wf2l, 512, 896);
    swl(W3, 1000,  400, W3h, W3l, 1024, 512);
    swl(W4, 2049, 1000, W4h, W4l, 2176, 1024);

    const int FT = F / 128;
    // ---- phase 1 ----
    mma_gemm<0><<<dim3(FT, 8), 256, SM>>>(Xh, Xl, 2112, W1h, W1l, 2112,
        b1, 1000, E1h, E1l, nullptr, 1024, 0, nullptr, nullptr, F);
    mma_gemm<0><<<dim3(FT, 4), 256, SM>>>(E1h, E1l, 1024, W2h, W2l, 1024,
        b2, 400, Cath, Catl, nullptr, 712, 200, nullptr, nullptr, F);
    mma_gemm<1><<<dim3(FT, 7), 256, SM>>>(Cath + 200, Catl + 200, 712,
        Wihh, Wihl, 512, bsum, 800, nullptr, nullptr, Gx, 896, 0,
        nullptr, nullptr, F);

    // ---- scan ----
    lstm_scan_kernel<<<8, 512>>>(Whh, Gx, Cath, Catl, F);

    // ---- phase 2 ----
    mma_gemm<0><<<dim3(FT, 7), 256, SM>>>(Cath, Catl, 712, Wf1h, Wf1l, 640,
        bf1, 800, T1h, T1l, nullptr, 896, 0, nullptr, nullptr, F);
    mma_gemm<0><<<dim3(FT, 4), 256, SM>>>(T1h, T1l, 896, Wf2h, Wf2l, 896,
        bf2, 400, T2h, T2l, nullptr, 512, 0, nullptr, nullptr, F);
    mma_gemm<0><<<dim3(FT, 8), 256, SM>>>(T2h, T2l, 512, W3h, W3l, 512,
        b3, 1000, Dh, Dl, nullptr, 1024, 0, nullptr, nullptr, F);
    mma_gemm<2><<<dim3(FT, 17), 256, SM>>>(Dh, Dl, 1024, W4h, W4l, 1024,
        b4, 2049, nullptr, nullptr, nullptr, 0, 0, mag, out, F);
}

// round 12
// speedup vs baseline: 3.2370x; 3.2370x over previous
#include <cuda_runtime.h>
#include <cuda_bf16.h>
#include <math.h>
#include <stdint.h>

typedef __nv_bfloat16 bf16;

// ---------------------------------------------------------------------------
// Frame-major dataflow, F = 8192:
//  magT(Xh/Xl)[F,2112] -> E1[F,1024] -> Cat[F,712] (H 0..200 | E 200..712)
//  -> Gx[F,896] f32 -> scan -> Cat H -> T1[F,896] -> T2[F,512] -> D[F,1024]
//  -> out[2049,F]
// bf16 hi/lo split (hi+lo ~ fp32@2^-17); weight pads ZERO.  GEMMs via
// mma.sync m16n8k16.  Scan: 128-thread 8-CTA cluster (R9-proven; >=256
// threads measured 3-4x slower sync — condemned).
// This round's single delta: GEMM chunk-(i+1) LDG prefetch behind HMMA.
// ---------------------------------------------------------------------------
#define FF 8192

__device__ __align__(16) bf16 g_Xh [FF * 2112], g_Xl [FF * 2112];
__device__ __align__(16) bf16 g_W1h[1024 * 2112], g_W1l[1024 * 2112];
__device__ __align__(16) bf16 g_W2h[ 512 * 1024], g_W2l[ 512 * 1024];
__device__ __align__(16) bf16 g_Wih_h[896 * 512], g_Wih_l[896 * 512];
__device__ __align__(16) bf16 g_Wf1h[896 * 640],  g_Wf1l[896 * 640];
__device__ __align__(16) bf16 g_Wf2h[512 * 896],  g_Wf2l[512 * 896];
__device__ __align__(16) bf16 g_W3h[1024 * 512],  g_W3l[1024 * 512];
__device__ __align__(16) bf16 g_W4h[2176 * 1024], g_W4l[2176 * 1024];
__device__ __align__(16) bf16 g_E1h[FF * 1024],   g_E1l[FF * 1024];
__device__ __align__(16) bf16 g_Cath[FF * 712],   g_Catl[FF * 712];
__device__ __align__(16) float g_Gx [FF * 896];
__device__ __align__(16) bf16 g_T1h[FF * 896],    g_T1l[FF * 896];
__device__ __align__(16) bf16 g_T2h[FF * 512],    g_T2l[FF * 512];
__device__ __align__(16) bf16 g_Dh [FF * 1024],   g_Dl [FF * 1024];
__device__ float g_bsum[800];

__device__ __forceinline__ float sigf(float x) { return 1.0f / (1.0f + expf(-x)); }
__device__ __forceinline__ float tanha(float x) {
    float y; asm("tanh.approx.f32 %0, %1;" : "=f"(y) : "f"(x)); return y;
}
__device__ __forceinline__ float siga(float x) {
    return 0.5f * tanha(0.5f * x) + 0.5f;
}
__device__ __forceinline__ uint32_t s2u(const void* p) {
    uint32_t a;
    asm("{ .reg .u64 t; cvta.to.shared.u64 t, %1; cvt.u32.u64 %0, t; }"
        : "=r"(a) : "l"(p));
    return a;
}
__device__ __forceinline__ void mbar_wait(uint32_t ba, uint32_t par) {
    uint32_t done;
    asm volatile(
        "{\n\t.reg .pred p;\n\t"
        "mbarrier.try_wait.parity.acquire.cta.shared::cta.b64 p, [%1], %2;\n\t"
        "selp.b32 %0, 1, 0, p;\n\t}"
        : "=r"(done) : "r"(ba), "r"(par) : "memory");
    if (!done) {
        asm volatile(
            "{\n\t.reg .pred P1;\n\t"
            "WL_%=:\n\t"
            "mbarrier.try_wait.parity.acquire.cta.shared::cta.b64 P1, [%0], %1, 0x989680;\n\t"
            "@P1 bra.uni WD_%=;\n\t"
            "bra.uni WL_%=;\n\t"
            "WD_%=:\n\t}"
            :: "r"(ba), "r"(par) : "memory");
    }
}
// packed f32x2 (scan)
__device__ __forceinline__ void fma2(unsigned long long& acc,
                                     unsigned long long a, unsigned long long b) {
    asm("fma.rn.f32x2 %0, %1, %2, %0;" : "+l"(acc) : "l"(a), "l"(b));
}
__device__ __forceinline__ unsigned long long pack2(float x, float y) {
    unsigned long long v;
    asm("mov.b64 %0, {%1, %2};" : "=l"(v) : "f"(x), "f"(y));
    return v;
}
__device__ __forceinline__ void unpack2(float& lo, float& hi, unsigned long long v) {
    asm("mov.b64 {%0, %1}, %2;" : "=f"(lo), "=f"(hi) : "l"(v));
}

// mma.sync m16n8k16 bf16 (row.col), f32 accum
__device__ __forceinline__ void mma16816(float d[4],
                                         uint32_t a0, uint32_t a1,
                                         uint32_t a2, uint32_t a3,
                                         uint32_t b0, uint32_t b1) {
    asm volatile(
        "mma.sync.aligned.m16n8k16.row.col.f32.bf16.bf16.f32 "
        "{%0,%1,%2,%3}, {%4,%5,%6,%7}, {%8,%9}, {%0,%1,%2,%3};"
        : "+f"(d[0]), "+f"(d[1]), "+f"(d[2]), "+f"(d[3])
        : "r"(a0), "r"(a1), "r"(a2), "r"(a3), "r"(b0), "r"(b1));
}

// ---------------------------------------------------------------------------
// mma_gemm<ACT>: D[128f x 128c] per CTA, 256 threads (8 warps, each 64x32).
// K in 64-chunks; pipeline: store chunk i regs->smem, sync, issue chunk
// i+1 LDGs (fly behind HMMA), compute chunk i, sync.  3 MMAs/tile (split).
// ---------------------------------------------------------------------------
template <int ACT>
__global__ void __launch_bounds__(256) mma_gemm(
    const bf16* __restrict__ Ah, const bf16* __restrict__ Al, int lda,
    const bf16* __restrict__ Wh, const bf16* __restrict__ Wl, int Kpad,
    const float* __restrict__ bias, int M,
    bf16* __restrict__ Chi, bf16* __restrict__ Clo, float* __restrict__ Cf,
    int ldc, int cofs,
    const float* __restrict__ mag, float* __restrict__ outp, int F)
{
    constexpr int P  = 72;   // smem pitch (bf16)
    constexpr int PW = 36;   // smem pitch (32-bit words)
    extern __shared__ bf16 smg[];
    bf16* sAh = smg;
    bf16* sAl = sAh + 128 * P;
    bf16* sWh = sAl + 128 * P;
    bf16* sWl = sWh + 128 * P;        // total 73728 B

    const int tid  = threadIdx.x;
    const int w    = tid >> 5;
    const int lane = tid & 31;
    const int g    = lane >> 2;
    const int tg   = lane & 3;
    const int wm   = (w & 1) * 64;
    const int wn   = (w >> 1) * 32;
    const int f0   = blockIdx.x * 128;
    const int m0   = blockIdx.y * 128;
    const int lrow = tid >> 1;
    const int lcol = (tid & 1) * 32;

    const uint32_t* s32Ah = reinterpret_cast<const uint32_t*>(sAh);
    const uint32_t* s32Al = reinterpret_cast<const uint32_t*>(sAl);
    const uint32_t* s32Wh = reinterpret_cast<const uint32_t*>(sWh);
    const uint32_t* s32Wl = reinterpret_cast<const uint32_t*>(sWl);

    float acc[4][4][4];
#pragma unroll
    for (int mt = 0; mt < 4; mt++)
#pragma unroll
        for (int nt = 0; nt < 4; nt++)
#pragma unroll
            for (int q = 0; q < 4; q++) acc[mt][nt][q] = 0.0f;

    uint4 rA[4], rB[4], rC[4], rD[4];
    auto load_regs = [&](int ci) {
        const int k0 = ci << 6;
        const uint4* pA = reinterpret_cast<const uint4*>(
            Ah + (size_t)(f0 + lrow) * lda + k0 + lcol);
        const uint4* pB = reinterpret_cast<const uint4*>(
            Al + (size_t)(f0 + lrow) * lda + k0 + lcol);
        const uint4* pC = reinterpret_cast<const uint4*>(
            Wh + (size_t)(m0 + lrow) * Kpad + k0 + lcol);
        const uint4* pD = reinterpret_cast<const uint4*>(
            Wl + (size_t)(m0 + lrow) * Kpad + k0 + lcol);
#pragma unroll
        for (int i = 0; i < 4; i++) {
            rA[i] = pA[i]; rB[i] = pB[i]; rC[i] = pC[i]; rD[i] = pD[i];
        }
    };
    auto store_regs = [&]() {
        uint4* dA = reinterpret_cast<uint4*>(sAh + lrow * P + lcol);
        uint4* dB = reinterpret_cast<uint4*>(sAl + lrow * P + lcol);
        uint4* dC = reinterpret_cast<uint4*>(sWh + lrow * P + lcol);
        uint4* dD = reinterpret_cast<uint4*>(sWl + lrow * P + lcol);
#pragma unroll
        for (int i = 0; i < 4; i++) {
            dA[i] = rA[i]; dB[i] = rB[i]; dC[i] = rC[i]; dD[i] = rD[i];
        }
    };

    const int NC = Kpad >> 6;
    load_regs(0);
    for (int ci = 0; ci < NC; ci++) {
        if (ci > 0) __syncthreads();          // compute of ci-1 done
        store_regs();
        __syncthreads();
        if (ci + 1 < NC) load_regs(ci + 1);   // LDGs fly behind HMMA

#pragma unroll
        for (int kk = 0; kk < 4; kk++) {
            uint32_t bh[4][2], bl[4][2];
#pragma unroll
            for (int nt = 0; nt < 4; nt++) {
                int br = (wn + nt * 8 + g) * PW + kk * 8 + tg;
                bh[nt][0] = s32Wh[br];      bh[nt][1] = s32Wh[br + 4];
                bl[nt][0] = s32Wl[br];      bl[nt][1] = s32Wl[br + 4];
            }
#pragma unroll
            for (int mt = 0; mt < 4; mt++) {
                int ar = (wm + mt * 16 + g) * PW + kk * 8 + tg;
                uint32_t ah0 = s32Ah[ar];
                uint32_t ah1 = s32Ah[ar + 8 * PW];
                uint32_t ah2 = s32Ah[ar + 4];
                uint32_t ah3 = s32Ah[ar + 8 * PW + 4];
                uint32_t al0 = s32Al[ar];
                uint32_t al1 = s32Al[ar + 8 * PW];
                uint32_t al2 = s32Al[ar + 4];
                uint32_t al3 = s32Al[ar + 8 * PW + 4];
#pragma unroll
                for (int nt = 0; nt < 4; nt++) {
                    mma16816(acc[mt][nt], ah0, ah1, ah2, ah3, bh[nt][0], bh[nt][1]);
                    mma16816(acc[mt][nt], al0, al1, al2, al3, bh[nt][0], bh[nt][1]);
                    mma16816(acc[mt][nt], ah0, ah1, ah2, ah3, bl[nt][0], bl[nt][1]);
                }
            }
        }
    }

    // ---- epilogue ----
#pragma unroll
    for (int mt = 0; mt < 4; mt++) {
        const int fa = f0 + wm + mt * 16 + g;
#pragma unroll
        for (int nt = 0; nt < 4; nt++) {
            const int c0 = m0 + wn + nt * 8 + 2 * tg;
            const float bv0 = (c0 < M)     ? __ldg(&bias[c0])     : 0.0f;
            const float bv1 = (c0 + 1 < M) ? __ldg(&bias[c0 + 1]) : 0.0f;
#pragma unroll
            for (int hrow = 0; hrow < 2; hrow++) {
                const int f = fa + hrow * 8;
                float v0 = acc[mt][nt][2 * hrow]     + bv0;
                float v1 = acc[mt][nt][2 * hrow + 1] + bv1;
                if (ACT == 0) {
                    v0 = (v0 >= 0.0f) ? v0 : 0.01f * v0;
                    v1 = (v1 >= 0.0f) ? v1 : 0.01f * v1;
                    bf16 h0 = __float2bfloat16(v0);
                    bf16 h1 = __float2bfloat16(v1);
                    bf16 l0 = __float2bfloat16(v0 - __bfloat162float(h0));
                    bf16 l1 = __float2bfloat16(v1 - __bfloat162float(h1));
                    uint32_t hw = ((uint32_t)__bfloat16_as_ushort(h1) << 16)
                                  | __bfloat16_as_ushort(h0);
                    uint32_t lw = ((uint32_t)__bfloat16_as_ushort(l1) << 16)
                                  | __bfloat16_as_ushort(l0);
                    size_t off = (size_t)f * ldc + cofs + c0;
                    *reinterpret_cast<uint32_t*>(Chi + off) = hw;
                    *reinterpret_cast<uint32_t*>(Clo + off) = lw;
                } else if (ACT == 1) {
                    *reinterpret_cast<float2*>(Cf + (size_t)f * ldc + c0) =
                        make_float2(v0, v1);
                } else {
                    if (c0 < 2049) {
                        size_t idx = (size_t)c0 * F + f;
                        outp[idx] = sigf(v0) * __ldg(&mag[idx]);
                    }
                    if (c0 + 1 < 2049) {
                        size_t idx = (size_t)(c0 + 1) * F + f;
                        outp[idx] = sigf(v1) * __ldg(&mag[idx]);
                    }
                }
            }
        }
    }
}

// ---------------------------------------------------------------------------
// prep kernels
// ---------------------------------------------------------------------------
__global__ void bias_sum_kernel(const float* __restrict__ a,
                                const float* __restrict__ b,
                                float* __restrict__ out, int n)
{
    int i = blockIdx.x * blockDim.x + threadIdx.x;
    if (i < n) out[i] = a[i] + b[i];
}

__global__ void split_weight(const float* __restrict__ W, int M, int K,
                             bf16* __restrict__ Wh, bf16* __restrict__ Wl,
                             int Mp, int Kp)
{
    int i = blockIdx.x * blockDim.x + threadIdx.x;
    if (i >= Mp * Kp) return;
    int r = i / Kp, c = i - r * Kp;
    float v = (r < M && c < K) ? W[(size_t)r * K + c] : 0.0f;
    bf16 h = __float2bfloat16(v);
    Wh[i] = h;
    Wl[i] = __float2bfloat16(v - __bfloat162float(h));
}

// mag[2049,F] -> Xh/Xl [F,2112] (transposed, split, zero-padded)
__global__ void transpose_split_mag(const float* __restrict__ mag,
                                    bf16* __restrict__ Xh, bf16* __restrict__ Xl,
                                    int F)
{
    __shared__ float sm[32][33];
    const int ft = blockIdx.x * 32, ct = blockIdx.y * 32;
    const int tx = threadIdx.x, ty = threadIdx.y;
#pragma unroll
    for (int i = 0; i < 4; i++) {
        int c = ct + ty + i * 8;
        sm[ty + i * 8][tx] = (c < 2049) ? mag[(size_t)c * F + ft + tx] : 0.0f;
    }
    __syncthreads();
#pragma unroll
    for (int i = 0; i < 4; i++) {
        int f = ft + ty + i * 8;
        int c = ct + tx;
        float v = sm[tx][ty + i * 8];
        bf16 h = __float2bfloat16(v);
        size_t idx = (size_t)f * 2112 + c;
        Xh[idx] = h;
        Xl[idx] = __float2bfloat16(v - __bfloat162float(h));
    }
}

// ---------------------------------------------------------------------------
// LSTM scan — VERBATIM round-9 (part of the 6547us PASS): 128 threads,
// 8-CTA cluster, whole W_hh row per thread (100 f32x2 regs), mbarrier
// ping-pong sync.
// ---------------------------------------------------------------------------
__global__ void __cluster_dims__(8, 1, 1) __launch_bounds__(128, 1)
lstm_scan_kernel(const float* __restrict__ Whh, const float* __restrict__ Gx,
                 bf16* __restrict__ CatH, bf16* __restrict__ CatL, int F)
{
    __shared__ __align__(16) float hbuf[2][200];
    __shared__ float sgate[100];
    __shared__ __align__(8) unsigned long long bars[2];

    const int tid  = threadIdx.x;
    const int rank = blockIdx.x;
    const bool valid = tid < 100;
    const int g    = tid / 25;
    const int j    = tid % 25;
    const int grow = 200 * g + 25 * rank + j;

    unsigned long long w[100];
    if (valid) {
        const float4* src = reinterpret_cast<const float4*>(Whh + (size_t)grow * 200);
#pragma unroll
        for (int k = 0; k < 50; k++) {
            float4 v = src[k];
            w[2 * k]     = pack2(v.x, v.y);
            w[2 * k + 1] = pack2(v.z, v.w);
        }
    } else {
#pragma unroll
        for (int k = 0; k < 100; k++) w[k] = 0ULL;
    }

    for (int i = tid; i < 400; i += 128)
        hbuf[i / 200][i % 200] = 0.0f;
    if (tid == 0) {
        asm volatile("mbarrier.init.shared.b64 [%0], 8;"
                     :: "r"(s2u(&bars[0])) : "memory");
        asm volatile("mbarrier.init.shared.b64 [%0], 8;"
                     :: "r"(s2u(&bars[1])) : "memory");
    }
    __syncthreads();

    const uint32_t hb_local  = s2u(&hbuf[0][0]);
    const uint32_t bar_delta = s2u(&bars[0]) - hb_local;
    uint32_t peer_h[8];
#pragma unroll
    for (int r = 0; r < 8; r++)
        asm("mapa.shared::cluster.u32 %0, %1, %2;"
            : "=r"(peer_h[r]) : "r"(hb_local), "r"(r));

    asm volatile("barrier.cluster.arrive.aligned;" ::: "memory");
    asm volatile("barrier.cluster.wait.aligned;"   ::: "memory");

    float c_state = 0.0f;
    float gx_cur = valid ? __ldg(&Gx[grow]) : 0.0f;
    int ph[2] = {0, 0};

    for (int t = 0; t < F; t++) {
        const int pb = t & 1;
        float gx_next = (valid && (t + 1 < F))
                          ? __ldg(&Gx[(size_t)(t + 1) * 896 + grow]) : 0.0f;

        if (valid) {
            const ulonglong2* h4 =
                reinterpret_cast<const ulonglong2*>(&hbuf[pb][0]);
            unsigned long long a0 = 0ULL, a1 = 0ULL, a2 = 0ULL, a3 = 0ULL;
#pragma unroll
            for (int k = 0; k < 25; k++) {
                ulonglong2 hA = h4[2 * k];
                ulonglong2 hB = h4[2 * k + 1];
                fma2(a0, w[4 * k],     hA.x);
                fma2(a1, w[4 * k + 1], hA.y);
                fma2(a2, w[4 * k + 2], hB.x);
                fma2(a3, w[4 * k + 3], hB.y);
            }
            float l0, h0, l1, h1, l2, h2, l3, h3;
            unpack2(l0, h0, a0); unpack2(l1, h1, a1);
            unpack2(l2, h2, a2); unpack2(l3, h3, a3);
            sgate[tid] = ((l0 + h0) + (l1 + h1)) + ((l2 + h2) + (l3 + h3))
                         + gx_cur;
        }
        gx_cur = gx_next;
        __syncthreads();

        if (tid < 25) {
            float gi = sgate[tid];
            float gf = sgate[25 + tid];
            float gg = sgate[50 + tid];
            float go = sgate[75 + tid];
            float cn = siga(gf) * c_state + siga(gi) * tanha(gg);
            float hn = siga(go) * tanha(cn);
            c_state = cn;
            size_t cidx = (size_t)t * 712 + 25 * rank + tid;
            bf16 hh = __float2bfloat16(hn);
            CatH[cidx] = hh;
            CatL[cidx] = __float2bfloat16(hn - __bfloat162float(hh));
            uint32_t off = (uint32_t)((((t + 1) & 1) * 200 + 25 * rank + tid) * 4);
#pragma unroll
            for (int r = 0; r < 8; r++)
                asm volatile("st.shared::cluster.f32 [%0], %1;"
                             :: "r"(peer_h[r] + off), "f"(hn) : "memory");
        }

        __syncthreads();   // drains DSMEM STS before the signal

        if (tid == 0) {
#pragma unroll
            for (int r = 0; r < 8; r++) {
                uint32_t ba = peer_h[r] + bar_delta + (uint32_t)(pb * 8);
                asm volatile("mbarrier.arrive.shared::cluster.b64 _, [%0];"
                             :: "r"(ba) : "memory");
            }
        }
        mbar_wait(s2u(&bars[pb]), (uint32_t)ph[pb]);
        ph[pb] ^= 1;
    }

    asm volatile("barrier.cluster.arrive.aligned;" ::: "memory");
    asm volatile("barrier.cluster.wait.aligned;"   ::: "memory");
}

// ---------------------------------------------------------------------------
// launch
// ---------------------------------------------------------------------------
extern "C" void kernel_launch(void* const* d_in, const int* in_sizes, int n_in,
                              void* d_out, int out_size)
{
    const float* mag = (const float*)d_in[0];
    const float* W1  = (const float*)d_in[1];
    const float* b1  = (const float*)d_in[2];
    const float* W2  = (const float*)d_in[3];
    const float* b2  = (const float*)d_in[4];
    const float* W3  = (const float*)d_in[5];
    const float* b3  = (const float*)d_in[6];
    const float* W4  = (const float*)d_in[7];
    const float* b4  = (const float*)d_in[8];
    const float* Wf1 = (const float*)d_in[9];
    const float* bf1 = (const float*)d_in[10];
    const float* Wf2 = (const float*)d_in[11];
    const float* bf2 = (const float*)d_in[12];
    const float* Wih = (const float*)d_in[13];
    const float* bih = (const float*)d_in[14];
    const float* Whh = (const float*)d_in[15];
    const float* bhh = (const float*)d_in[16];

    const int F = in_sizes[0] / 2049;
    float* out = (float*)d_out;

    bf16 *Xh, *Xl, *W1h, *W1l, *W2h, *W2l, *Wihh, *Wihl, *Wf1h, *Wf1l;
    bf16 *Wf2h, *Wf2l, *W3h, *W3l, *W4h, *W4l;
    bf16 *E1h, *E1l, *Cath, *Catl, *T1h, *T1l, *T2h, *T2l, *Dh, *Dl;
    float *Gx, *bsum;
    cudaGetSymbolAddress((void**)&Xh, g_Xh);     cudaGetSymbolAddress((void**)&Xl, g_Xl);
    cudaGetSymbolAddress((void**)&W1h, g_W1h);   cudaGetSymbolAddress((void**)&W1l, g_W1l);
    cudaGetSymbolAddress((void**)&W2h, g_W2h);   cudaGetSymbolAddress((void**)&W2l, g_W2l);
    cudaGetSymbolAddress((void**)&Wihh, g_Wih_h);cudaGetSymbolAddress((void**)&Wihl, g_Wih_l);
    cudaGetSymbolAddress((void**)&Wf1h, g_Wf1h); cudaGetSymbolAddress((void**)&Wf1l, g_Wf1l);
    cudaGetSymbolAddress((void**)&Wf2h, g_Wf2h); cudaGetSymbolAddress((void**)&Wf2l, g_Wf2l);
    cudaGetSymbolAddress((void**)&W3h, g_W3h);   cudaGetSymbolAddress((void**)&W3l, g_W3l);
    cudaGetSymbolAddress((void**)&W4h, g_W4h);   cudaGetSymbolAddress((void**)&W4l, g_W4l);
    cudaGetSymbolAddress((void**)&E1h, g_E1h);   cudaGetSymbolAddress((void**)&E1l, g_E1l);
    cudaGetSymbolAddress((void**)&Cath, g_Cath); cudaGetSymbolAddress((void**)&Catl, g_Catl);
    cudaGetSymbolAddress((void**)&T1h, g_T1h);   cudaGetSymbolAddress((void**)&T1l, g_T1l);
    cudaGetSymbolAddress((void**)&T2h, g_T2h);   cudaGetSymbolAddress((void**)&T2l, g_T2l);
    cudaGetSymbolAddress((void**)&Dh, g_Dh);     cudaGetSymbolAddress((void**)&Dl, g_Dl);
    cudaGetSymbolAddress((void**)&Gx, g_Gx);
    cudaGetSymbolAddress((void**)&bsum, g_bsum);

    const int SM = 4 * 128 * 72 * 2;   // 73728 B
    cudaFuncSetAttribute(mma_gemm<0>, cudaFuncAttributeMaxDynamicSharedMemorySize, SM);
    cudaFuncSetAttribute(mma_gemm<1>, cudaFuncAttributeMaxDynamicSharedMemorySize, SM);
    cudaFuncSetAttribute(mma_gemm<2>, cudaFuncAttributeMaxDynamicSharedMemorySize, SM);

    // ---- prep ----
    bias_sum_kernel<<<4, 256>>>(bih, bhh, bsum, 800);
    transpose_split_mag<<<dim3(F / 32, 66), dim3(32, 8)>>>(mag, Xh, Xl, F);
    auto swl = [&](const float* W, int M, int K, bf16* Wh_, bf16* Wl_, int Mp, int Kp) {
        split_weight<<<(Mp * Kp + 255) / 256, 256>>>(W, M, K, Wh_, Wl_, Mp, Kp);
    };
    swl(W1, 1000, 2049, W1h, W1l, 1024, 2112);
    swl(W2,  400, 1000, W2h, W2l,  512, 1024);
    swl(Wih, 800,  400, Wihh, Wihl, 896, 512);
    swl(Wf1, 800,  600, Wf1h, Wf1l, 896, 640);
    swl(Wf2, 400,  800, Wf2h, Wf2l, 512, 896);
    swl(W3, 1000,  400, W3h, W3l, 1024, 512);
    swl(W4, 2049, 1000, W4h, W4l, 2176, 1024);

    const int FT = F / 128;
    // ---- phase 1 ----
    mma_gemm<0><<<dim3(FT, 8), 256, SM>>>(Xh, Xl, 2112, W1h, W1l, 2112,
        b1, 1000, E1h, E1l, nullptr, 1024, 0, nullptr, nullptr, F);
    mma_gemm<0><<<dim3(FT, 4), 256, SM>>>(E1h, E1l, 1024, W2h, W2l, 1024,
        b2, 400, Cath, Catl, nullptr, 712, 200, nullptr, nullptr, F);
    mma_gemm<1><<<dim3(FT, 7), 256, SM>>>(Cath + 200, Catl + 200, 712,
        Wihh, Wihl, 512, bsum, 800, nullptr, nullptr, Gx, 896, 0,
        nullptr, nullptr, F);

    // ---- scan ----
    lstm_scan_kernel<<<8, 128>>>(Whh, Gx, Cath, Catl, F);

    // ---- phase 2 ----
    mma_gemm<0><<<dim3(FT, 7), 256, SM>>>(Cath, Catl, 712, Wf1h, Wf1l, 640,
        bf1, 800, T1h, T1l, nullptr, 896, 0, nullptr, nullptr, F);
    mma_gemm<0><<<dim3(FT, 4), 256, SM>>>(T1h, T1l, 896, Wf2h, Wf2l, 896,
        bf2, 400, T2h, T2l, nullptr, 512, 0, nullptr, nullptr, F);
    mma_gemm<0><<<dim3(FT, 8), 256, SM>>>(T2h, T2l, 512, W3h, W3l, 512,
        b3, 1000, Dh, Dl, nullptr, 1024, 0, nullptr, nullptr, F);
    mma_gemm<2><<<dim3(FT, 17), 256, SM>>>(Dh, Dl, 1024, W4h, W4l, 1024,
        b4, 2049, nullptr, nullptr, nullptr, 0, 0, mag, out, F);
}